// round 1
// baseline (speedup 1.0000x reference)
#include <cuda_runtime.h>
#include <math.h>

#define NB 64      // batch
#define NT 1024    // seq len
#define ND 256     // input dim
#define NH 1024    // hidden
#define NC 1000    // classes

#define RCTAS 128  // persistent recurrence CTAs (<=148 SMs, 1 CTA/SM guaranteed resident)

// ---------------- scratch (device globals; no allocation allowed) ----------------
__device__ float g_xproj[NT * NB * NH];   // [t][b][h]  (256 MB)
__device__ float g_h[NB * NH];            // current hidden state [b][h]
__device__ float g_zpart[8 * NB * NH];    // split-K partials: 8 k-chunks of [b][n]
__device__ unsigned g_bar_count;
__device__ unsigned g_bar_gen;

// ---------------- software grid barrier (all CTAs co-resident) ----------------
__device__ __forceinline__ void gsync(unsigned nb) {
    __syncthreads();
    if (threadIdx.x == 0) {
        __threadfence();                                   // release our writes
        unsigned g = atomicOr(&g_bar_gen, 0u);             // read current generation
        if (atomicAdd(&g_bar_count, 1u) == nb - 1u) {
            atomicExch(&g_bar_count, 0u);
            __threadfence();
            atomicExch(&g_bar_gen, g + 1u);                // release
        } else {
            while (atomicOr(&g_bar_gen, 0u) == g) { __nanosleep(64); }
        }
        __threadfence();                                   // acquire
    }
    __syncthreads();
}

// ---------------- 64x64 output tile fp32 GEMM core ----------------
// C[64,64] += A[64,K] * B[64,K]^T ; 256 threads, 4x4 microtile per thread.
// A rows assumed full 64; B rows clamped to brows (for the FC N=1000 edge).
// All global loads bypass L1 (__ldcg) — required for cross-SM coherence in the
// persistent recurrence kernel (L1 is not coherent within a launch).
__device__ __forceinline__ void mm_tile(
    const float* A, int lda,
    const float* B, int ldb, int brows,
    int K, float acc[4][4],
    float (*As)[64], float (*Bs)[64])
{
    const int tid = threadIdx.x;
    const int tx = tid & 15, ty = tid >> 4;
    const int lr = tid >> 2, lc = tid & 3;
    const int br = (lr < brows) ? lr : (brows - 1);
    const float* Arow = A + lr * lda;
    const float* Brow = B + br * ldb;

    for (int k0 = 0; k0 < K; k0 += 32) {
        float4 a0 = __ldcg((const float4*)(Arow + k0 + lc * 4));
        float4 a1 = __ldcg((const float4*)(Arow + k0 + 16 + lc * 4));
        float4 b0 = __ldcg((const float4*)(Brow + k0 + lc * 4));
        float4 b1 = __ldcg((const float4*)(Brow + k0 + 16 + lc * 4));
        __syncthreads();   // previous chunk's consumers done
        As[lc * 4 + 0][lr] = a0.x;  As[lc * 4 + 1][lr] = a0.y;
        As[lc * 4 + 2][lr] = a0.z;  As[lc * 4 + 3][lr] = a0.w;
        As[lc * 4 + 16][lr] = a1.x; As[lc * 4 + 17][lr] = a1.y;
        As[lc * 4 + 18][lr] = a1.z; As[lc * 4 + 19][lr] = a1.w;
        Bs[lc * 4 + 0][lr] = b0.x;  Bs[lc * 4 + 1][lr] = b0.y;
        Bs[lc * 4 + 2][lr] = b0.z;  Bs[lc * 4 + 3][lr] = b0.w;
        Bs[lc * 4 + 16][lr] = b1.x; Bs[lc * 4 + 17][lr] = b1.y;
        Bs[lc * 4 + 18][lr] = b1.z; Bs[lc * 4 + 19][lr] = b1.w;
        __syncthreads();
        #pragma unroll
        for (int kk = 0; kk < 32; kk++) {
            float4 av = *(const float4*)(&As[kk][ty * 4]);
            float4 bv = *(const float4*)(&Bs[kk][tx * 4]);
            float a[4] = {av.x, av.y, av.z, av.w};
            float b[4] = {bv.x, bv.y, bv.z, bv.w};
            #pragma unroll
            for (int i = 0; i < 4; i++)
                #pragma unroll
                for (int j = 0; j < 4; j++)
                    acc[i][j] += a[i] * b[j];
        }
    }
}

// ---------------- kernel 1: xproj[t][b][h] = x[b][t][:] . w_ih[h][:] ----------------
// M = B*T = 65536 rows (m = b*1024 + t), N = 1024, K = 256. Stores transposed to [t][b][h].
__global__ __launch_bounds__(256) void xproj_kernel(
    const float* __restrict__ x, const float* __restrict__ w_ih)
{
    __shared__ float As[32][64];
    __shared__ float Bs[32][64];
    const int m0 = blockIdx.x * 64;
    const int n0 = blockIdx.y * 64;
    float acc[4][4] = {};
    mm_tile(x + (long)m0 * ND, ND, w_ih + (long)n0 * ND, ND, 64, ND, acc, As, Bs);

    const int tid = threadIdx.x;
    const int tx = tid & 15, ty = tid >> 4;
    #pragma unroll
    for (int i = 0; i < 4; i++) {
        int m = m0 + ty * 4 + i;
        int b = m >> 10;          // batch
        int t = m & 1023;         // timestep
        float4 v = make_float4(acc[i][0], acc[i][1], acc[i][2], acc[i][3]);
        *(float4*)(g_xproj + ((long)t * NB + b) * NH + n0 + tx * 4) = v;
    }
}

// ---------------- kernel 2: persistent recurrence ----------------
// 128 CTAs: nc = cta&15 (64 output cols), kc = cta>>4 (128-wide K chunk).
// Per step: phase1 partial GEMM -> zpart ; gsync ; phase2 reduce + modReLU -> h ; gsync.
__global__ __launch_bounds__(256) void recur_kernel(
    const float* __restrict__ w_hh, const float* __restrict__ b_mod)
{
    __shared__ float As[32][64];
    __shared__ float Bs[32][64];
    const int tid = threadIdx.x;
    const int cta = blockIdx.x;
    const int nc = cta & 15;
    const int kc = cta >> 4;
    const int tx = tid & 15, ty = tid >> 4;

    // h = 0
    for (int i = cta * 256 + tid; i < NB * NH; i += RCTAS * 256) g_h[i] = 0.0f;
    gsync(RCTAS);

    const float* Abase = g_h + kc * 128;                       // h[:, kc*128 : +128]
    const float* Bbase = w_hh + (long)(nc * 64) * NH + kc * 128;
    float* zbase = g_zpart + (long)kc * (NB * NH) + nc * 64;

    for (int t = 0; t < NT; t++) {
        // ---- phase 1: partial GEMM over this CTA's K chunk ----
        float acc[4][4] = {};
        mm_tile(Abase, NH, Bbase, NH, 64, 128, acc, As, Bs);
        #pragma unroll
        for (int i = 0; i < 4; i++) {
            float4 v = make_float4(acc[i][0], acc[i][1], acc[i][2], acc[i][3]);
            *(float4*)(zbase + (long)(ty * 4 + i) * NH + tx * 4) = v;
        }
        gsync(RCTAS);

        // ---- phase 2: reduce 8 partials + xproj, modReLU, write h ----
        const float* xp = g_xproj + (long)t * (NB * NH);
        #pragma unroll
        for (int r = 0; r < 2; r++) {
            int idx = cta * 512 + r * 256 + tid;               // = b*1024 + n
            float z = __ldg(&xp[idx]);
            #pragma unroll
            for (int s = 0; s < 8; s++)
                z += __ldcg(&g_zpart[(long)s * (NB * NH) + idx]);
            float bm = __ldg(&b_mod[idx & 1023]);
            float az = fabsf(z) + bm;
            g_h[idx] = (az > 0.0f) ? copysignf(az, z) : 0.0f;
        }
        gsync(RCTAS);
    }
}

// ---------------- kernel 3: fc head  out[b][c] = h[b][:] . w_fc[c][:] + b_fc[c] ----------------
__global__ __launch_bounds__(256) void fc_kernel(
    const float* __restrict__ w_fc, const float* __restrict__ b_fc,
    float* __restrict__ out)
{
    __shared__ float As[32][64];
    __shared__ float Bs[32][64];
    const int n0 = blockIdx.x * 64;
    int brows = NC - n0; if (brows > 64) brows = 64;
    float acc[4][4] = {};
    mm_tile(g_h, NH, w_fc + (long)n0 * NH, NH, brows, NH, acc, As, Bs);

    const int tid = threadIdx.x;
    const int tx = tid & 15, ty = tid >> 4;
    #pragma unroll
    for (int i = 0; i < 4; i++) {
        int m = ty * 4 + i;
        #pragma unroll
        for (int j = 0; j < 4; j++) {
            int n = n0 + tx * 4 + j;
            if (n < NC) out[(long)m * NC + n] = acc[i][j] + __ldg(&b_fc[n]);
        }
    }
}

// ---------------- launch ----------------
extern "C" void kernel_launch(void* const* d_in, const int* in_sizes, int n_in,
                              void* d_out, int out_size)
{
    const float* x     = (const float*)d_in[0];  // [64,1024,256]
    const float* w_ih  = (const float*)d_in[1];  // [1024,256]
    const float* w_hh  = (const float*)d_in[2];  // [1024,1024]
    const float* b_mod = (const float*)d_in[3];  // [1024]
    const float* w_fc  = (const float*)d_in[4];  // [1000,1024]
    const float* b_fc  = (const float*)d_in[5];  // [1000]
    float* out = (float*)d_out;                  // [64,1000]

    dim3 gx((NB * NT) / 64, NH / 64);            // 1024 x 16
    xproj_kernel<<<gx, 256>>>(x, w_ih);
    recur_kernel<<<RCTAS, 256>>>(w_hh, b_mod);
    fc_kernel<<<(NC + 63) / 64, 256>>>(w_fc, b_fc, out);
}